// round 1
// baseline (speedup 1.0000x reference)
#include <cuda_runtime.h>
#include <cuda_bf16.h>

// ---------------------------------------------------------------------------
// LocalWLNet: embed->GN -> GCN(32->32)+GN+ReLU -> GCN(32->24)+GN
//             -> pair mult -> [GCN(24->24)+GN+ReLU] fwd + rev, sum
//             -> idx gather, even*odd, dot pw + pb
// All fp32. Scratch in __device__ globals (no allocation).
// ---------------------------------------------------------------------------

#define MAXN 100000
#define MAXP 1000000

__device__ float g_nodeA[MAXN * 32];
__device__ float g_nodeB[MAXN * 32];
__device__ float g_nodeC[MAXN * 32];
__device__ float g_pairX[MAXP * 24];
__device__ float g_pairH[MAXP * 24];
__device__ float g_pairA[MAXP * 24];
__device__ float g_pairB[MAXP * 24];
__device__ float g_dinv1[MAXN];
__device__ float g_dinv2a[MAXP];
__device__ float g_dinv2b[MAXP];
__device__ double g_stats[6 * 64];  // per norm: [0:32) sum, [32:64) sumsq

#define EPSV 1e-5f

static inline int GRID(long long n, int b) { return (int)((n + b - 1) / b); }

// ---------------- degree ----------------
__global__ void k_count(const int* __restrict__ dst, int E, float* deg) {
    int i = blockIdx.x * blockDim.x + threadIdx.x;
    if (i < E) atomicAdd(&deg[dst[i]], 1.0f);
}

__global__ void k_finish_deg(float* deg, int n) {
    int i = blockIdx.x * blockDim.x + threadIdx.x;
    if (i < n) deg[i] = rsqrtf(deg[i] + 1.0f);  // self-loop included
}

// ---------------- embedding gather (float4 groups) ----------------
__global__ void k_embed(const int* __restrict__ ids, const float* __restrict__ emb,
                        float* __restrict__ out, int n) {
    int t = blockIdx.x * blockDim.x + threadIdx.x;
    if (t >= n * 8) return;
    int r = t >> 3, g = t & 7;
    float4 v = *(const float4*)(emb + (size_t)ids[r] * 32 + g * 4);
    *(float4*)(out + (size_t)r * 32 + g * 4) = v;
}

// ---------------- graph_norm stats: per-column sum & sumsq ----------------
__global__ void k_stats(const float* __restrict__ x, int n, int C, double* st) {
    int c = threadIdx.x;   // < C
    int ty = threadIdx.y;  // < 8
    double s = 0.0, s2 = 0.0;
    for (int r = blockIdx.x * blockDim.y + ty; r < n; r += gridDim.x * blockDim.y) {
        float v = x[(size_t)r * C + c];
        s += v;
        s2 += (double)v * (double)v;
    }
    __shared__ double sh[2][8][32];
    sh[0][ty][c] = s;
    sh[1][ty][c] = s2;
    __syncthreads();
    if (ty == 0) {
        for (int t = 1; t < blockDim.y; t++) { s += sh[0][t][c]; s2 += sh[1][t][c]; }
        atomicAdd(&st[c], s);
        atomicAdd(&st[32 + c], s2);
    }
}

// ---------------- graph_norm apply (in place), optional relu ----------------
__global__ void k_apply(float* __restrict__ x, int n, int C, const double* __restrict__ st,
                        const float* __restrict__ w, const float* __restrict__ b,
                        const float* __restrict__ a, int relu) {
    long long i = (long long)blockIdx.x * blockDim.x + threadIdx.x;
    if (i >= (long long)n * C) return;
    int c = (int)(i % C);
    double av = (double)a[c];
    double m = st[c] / n;
    double var = st[32 + c] / n - m * m * av * (2.0 - av);
    float inv = rsqrtf((float)var + EPSV);
    float v = w[c] * (x[i] - (float)(av * m)) * inv + b[c];
    if (relu) v = fmaxf(v, 0.0f);
    x[i] = v;
}

// ---------------- h = x @ W (thread per row, W in shared) ----------------
template <int CIN, int COUT>
__global__ void k_mm(const float* __restrict__ x, const float* __restrict__ W,
                     float* __restrict__ h, int n) {
    __shared__ float Ws[CIN * COUT];
    for (int t = threadIdx.x; t < CIN * COUT; t += blockDim.x) Ws[t] = W[t];
    __syncthreads();
    int i = blockIdx.x * blockDim.x + threadIdx.x;
    if (i >= n) return;
    float acc[COUT];
#pragma unroll
    for (int j = 0; j < COUT; j++) acc[j] = 0.0f;
    const float* xr = x + (size_t)i * CIN;
#pragma unroll
    for (int k = 0; k < CIN; k++) {
        float xv = xr[k];
#pragma unroll
        for (int j = 0; j < COUT; j++) acc[j] += xv * Ws[k * COUT + j];
    }
    float* hr = h + (size_t)i * COUT;
#pragma unroll
    for (int j = 0; j < COUT; j++) hr[j] = acc[j];
}

// ---------------- out = dinv^2 * h + bias (self loop init) ----------------
__global__ void k_self(const float* __restrict__ h, const float* __restrict__ dinv,
                       const float* __restrict__ b, float* __restrict__ out, int n, int C) {
    long long i = (long long)blockIdx.x * blockDim.x + threadIdx.x;
    if (i >= (long long)n * C) return;
    int r = (int)(i / C), c = (int)(i % C);
    float dv = dinv[r];
    out[i] = dv * dv * h[i] + b[c];
}

// ---------------- edge scatter: out[d] += dinv[s]*dinv[d] * h[s] ----------
// 8 float4-groups per edge; for C=24 only first 6 groups active.
template <int C>
__global__ void k_scatter(const int* __restrict__ src, const int* __restrict__ dst,
                          const float* __restrict__ dinv, const float* __restrict__ h,
                          float* __restrict__ out, int E) {
    long long t = (long long)blockIdx.x * blockDim.x + threadIdx.x;
    int e = (int)(t >> 3);
    int g = (int)(t & 7);
    if (e >= E) return;
    if (C == 24 && g >= 6) return;
    int s = src[e], d = dst[e];
    float coef = dinv[s] * dinv[d];
    float4 v = *(const float4*)(h + (size_t)s * C + g * 4);
    float4 r;
    r.x = v.x * coef; r.y = v.y * coef; r.z = v.z * coef; r.w = v.w * coef;
    atomicAdd((float4*)(out + (size_t)d * C + g * 4), r);  // sm_90+ vector RED
}

// ---------------- pair features: x = xn[pos0] * xn[pos1], C=24 ------------
__global__ void k_pair(const int* __restrict__ pos, const float* __restrict__ xn,
                       float* __restrict__ out, int P) {
    long long t = (long long)blockIdx.x * blockDim.x + threadIdx.x;
    int p = (int)(t >> 3);
    int g = (int)(t & 7);
    if (p >= P || g >= 6) return;
    int a = pos[2 * p], b = pos[2 * p + 1];
    float4 va = *(const float4*)(xn + (size_t)a * 24 + g * 4);
    float4 vb = *(const float4*)(xn + (size_t)b * 24 + g * 4);
    float4 r;
    r.x = va.x * vb.x; r.y = va.y * vb.y; r.z = va.z * vb.z; r.w = va.w * vb.w;
    *(float4*)(out + (size_t)p * 24 + g * 4) = r;
}

// ---------------- combine: relu(norm_A(A)) + relu(norm_B(B)) --------------
__global__ void k_combine(const float* __restrict__ A, const float* __restrict__ B, int n,
                          const double* __restrict__ stA, const double* __restrict__ stB,
                          const float* __restrict__ wA, const float* __restrict__ bA,
                          const float* __restrict__ aA, const float* __restrict__ wB,
                          const float* __restrict__ bB, const float* __restrict__ aB,
                          float* __restrict__ out) {
    long long i = (long long)blockIdx.x * blockDim.x + threadIdx.x;
    if (i >= (long long)n * 24) return;
    int c = (int)(i % 24);

    double avA = (double)aA[c];
    double mA = stA[c] / n;
    double vA = stA[32 + c] / n - mA * mA * avA * (2.0 - avA);
    float xa = wA[c] * (A[i] - (float)(avA * mA)) * rsqrtf((float)vA + EPSV) + bA[c];
    xa = fmaxf(xa, 0.0f);

    double avB = (double)aB[c];
    double mB = stB[c] / n;
    double vB = stB[32 + c] / n - mB * mB * avB * (2.0 - avB);
    float xb = wB[c] * (B[i] - (float)(avB * mB)) * rsqrtf((float)vB + EPSV) + bB[c];
    xb = fmaxf(xb, 0.0f);

    out[i] = xa + xb;
}

// ---------------- head: out[m] = dot(xs[idx[2m]]*xs[idx[2m+1]], pw)+pb ----
__global__ void k_final(const int* __restrict__ idx, const float* __restrict__ xs,
                        const float* __restrict__ pw, const float* __restrict__ pb,
                        float* __restrict__ out, int M) {
    long long t = (long long)blockIdx.x * blockDim.x + threadIdx.x;
    int m = (int)(t >> 5);
    int lane = (int)(t & 31);
    if (m >= M) return;
    int ia = idx[2 * m], ib = idx[2 * m + 1];
    float v = 0.0f;
    if (lane < 24) v = xs[(size_t)ia * 24 + lane] * xs[(size_t)ib * 24 + lane] * pw[lane];
#pragma unroll
    for (int o = 16; o > 0; o >>= 1) v += __shfl_down_sync(0xffffffffu, v, o);
    if (lane == 0) out[m] = v + pb[0];
}

// ---------------------------------------------------------------------------
extern "C" void kernel_launch(void* const* d_in, const int* in_sizes, int n_in,
                              void* d_out, int out_size) {
    const int* x_ids = (const int*)d_in[0];
    const int* edge1 = (const int*)d_in[1];
    const int* pos   = (const int*)d_in[2];
    const int* ei2   = (const int*)d_in[3];
    const int* idx   = (const int*)d_in[4];
    const float* emb = (const float*)d_in[5];
    const float *gn0w = (const float*)d_in[6], *gn0b = (const float*)d_in[7], *gn0a = (const float*)d_in[8];
    const float *c1w0 = (const float*)d_in[9], *c1b0 = (const float*)d_in[10];
    const float *gn1w0 = (const float*)d_in[11], *gn1b0 = (const float*)d_in[12], *gn1a0 = (const float*)d_in[13];
    const float *c1w1 = (const float*)d_in[14], *c1b1 = (const float*)d_in[15];
    const float *gn1w1 = (const float*)d_in[16], *gn1b1 = (const float*)d_in[17], *gn1a1 = (const float*)d_in[18];
    const float *c2w = (const float*)d_in[19], *c2b = (const float*)d_in[20];
    const float *gn2w = (const float*)d_in[21], *gn2b = (const float*)d_in[22], *gn2a = (const float*)d_in[23];
    const float *c2rw = (const float*)d_in[24], *c2rb = (const float*)d_in[25];
    const float *gn2rw = (const float*)d_in[26], *gn2rb = (const float*)d_in[27], *gn2ra = (const float*)d_in[28];
    const float *pw = (const float*)d_in[29], *pb = (const float*)d_in[30];

    const int N  = in_sizes[0];
    const int E1 = in_sizes[1] / 2;
    const int P  = in_sizes[2] / 2;
    const int E2 = in_sizes[3] / 2;
    const int M  = P / 2;

    float *nodeA, *nodeB, *nodeC, *pairX, *pairH, *pairA, *pairB;
    float *dinv1, *dinv2a, *dinv2b;
    double* stats;
    cudaGetSymbolAddress((void**)&nodeA, g_nodeA);
    cudaGetSymbolAddress((void**)&nodeB, g_nodeB);
    cudaGetSymbolAddress((void**)&nodeC, g_nodeC);
    cudaGetSymbolAddress((void**)&pairX, g_pairX);
    cudaGetSymbolAddress((void**)&pairH, g_pairH);
    cudaGetSymbolAddress((void**)&pairA, g_pairA);
    cudaGetSymbolAddress((void**)&pairB, g_pairB);
    cudaGetSymbolAddress((void**)&dinv1, g_dinv1);
    cudaGetSymbolAddress((void**)&dinv2a, g_dinv2a);
    cudaGetSymbolAddress((void**)&dinv2b, g_dinv2b);
    cudaGetSymbolAddress((void**)&stats, g_stats);

    const int B = 256;

    // zero scratch accumulators
    cudaMemsetAsync(dinv1, 0, (size_t)N * sizeof(float));
    cudaMemsetAsync(dinv2a, 0, (size_t)P * sizeof(float));
    cudaMemsetAsync(dinv2b, 0, (size_t)P * sizeof(float));
    cudaMemsetAsync(stats, 0, 6 * 64 * sizeof(double));

    // degrees (dst side, +1 self loop), -> deg^-1/2
    k_count<<<GRID(E1, B), B>>>(edge1 + E1, E1, dinv1);
    k_count<<<GRID(E2, B), B>>>(ei2 + E2, E2, dinv2a);   // xa: dst = ei2[1]
    k_count<<<GRID(E2, B), B>>>(ei2, E2, dinv2b);        // xb: dst = ei2[0]
    k_finish_deg<<<GRID(N, B), B>>>(dinv1, N);
    k_finish_deg<<<GRID(P, B), B>>>(dinv2a, P);
    k_finish_deg<<<GRID(P, B), B>>>(dinv2b, P);

    // embedding + GraphNorm0
    k_embed<<<GRID((long long)N * 8, B), B>>>(x_ids, emb, nodeA, N);
    k_stats<<<256, dim3(32, 8)>>>(nodeA, N, 32, stats + 0);
    k_apply<<<GRID((long long)N * 32, B), B>>>(nodeA, N, 32, stats + 0, gn0w, gn0b, gn0a, 0);

    // conv1 layer0: 32->32, GN, ReLU
    k_mm<32, 32><<<GRID(N, B), B>>>(nodeA, c1w0, nodeB, N);
    k_self<<<GRID((long long)N * 32, B), B>>>(nodeB, dinv1, c1b0, nodeC, N, 32);
    k_scatter<32><<<GRID((long long)E1 * 8, B), B>>>(edge1, edge1 + E1, dinv1, nodeB, nodeC, E1);
    k_stats<<<256, dim3(32, 8)>>>(nodeC, N, 32, stats + 64);
    k_apply<<<GRID((long long)N * 32, B), B>>>(nodeC, N, 32, stats + 64, gn1w0, gn1b0, gn1a0, 1);

    // conv1 layer1: 32->24, GN
    k_mm<32, 24><<<GRID(N, B), B>>>(nodeC, c1w1, nodeA, N);
    k_self<<<GRID((long long)N * 24, B), B>>>(nodeA, dinv1, c1b1, nodeB, N, 24);
    k_scatter<24><<<GRID((long long)E1 * 8, B), B>>>(edge1, edge1 + E1, dinv1, nodeA, nodeB, E1);
    k_stats<<<256, dim3(24, 8)>>>(nodeB, N, 24, stats + 128);
    k_apply<<<GRID((long long)N * 24, B), B>>>(nodeB, N, 24, stats + 128, gn1w1, gn1b1, gn1a1, 0);

    // pair features
    k_pair<<<GRID((long long)P * 8, B), B>>>(pos, nodeB, pairX, P);

    // conv2 forward: 24->24
    k_mm<24, 24><<<GRID(P, B), B>>>(pairX, c2w, pairH, P);
    k_self<<<GRID((long long)P * 24, B), B>>>(pairH, dinv2a, c2b, pairA, P, 24);
    k_scatter<24><<<GRID((long long)E2 * 8, B), B>>>(ei2, ei2 + E2, dinv2a, pairH, pairA, E2);
    k_stats<<<512, dim3(24, 8)>>>(pairA, P, 24, stats + 192);

    // conv2 reversed: 24->24
    k_mm<24, 24><<<GRID(P, B), B>>>(pairX, c2rw, pairH, P);
    k_self<<<GRID((long long)P * 24, B), B>>>(pairH, dinv2b, c2rb, pairB, P, 24);
    k_scatter<24><<<GRID((long long)E2 * 8, B), B>>>(ei2 + E2, ei2, dinv2b, pairH, pairB, E2);
    k_stats<<<512, dim3(24, 8)>>>(pairB, P, 24, stats + 256);

    // relu(norm(A)) + relu(norm(B)) -> pairX
    k_combine<<<GRID((long long)P * 24, B), B>>>(pairA, pairB, P, stats + 192, stats + 256,
                                                 gn2w, gn2b, gn2a, gn2rw, gn2rb, gn2ra, pairX);

    // head
    k_final<<<GRID((long long)M * 32, B), B>>>(idx, pairX, pw, pb, (float*)d_out, M);
}

// round 2
// speedup vs baseline: 1.2612x; 1.2612x over previous
#include <cuda_runtime.h>
#include <cuda_bf16.h>

// ---------------------------------------------------------------------------
// LocalWLNet, CSR-based (no float atomics):
//   embed -> [GN0 folded] mm(32x32) -> csr-gather(+self+bias) -> stats
//   -> [GN1_0+relu folded] mm(32x24) -> csr-gather -> stats
//   -> pair(+GN1_1 folded)+dual mm(24x24) -> csr-gather fwd/rev -> stats
//   -> combine(GN2 fwd/rev + relu + sum) -> head
// ---------------------------------------------------------------------------

#define MAXN   100000
#define MAXP   1000000
#define MAXE1  3200000
#define MAXE2  4000000
#define EPSV   1e-5f

__device__ float g_node0[MAXN * 32];
__device__ float g_node1[MAXN * 32];
__device__ float g_node2[MAXN * 32];
__device__ float g_pairHa[MAXP * 24];
__device__ float g_pairHb[MAXP * 24];
__device__ float g_pairA[MAXP * 24];
__device__ float g_pairB[MAXP * 24];

__device__ int   g_cnt1[MAXN],  g_off1[MAXN + 1],  g_cur1[MAXN];
__device__ int   g_cnt2f[MAXP], g_off2f[MAXP + 1], g_cur2f[MAXP];
__device__ int   g_cnt2r[MAXP], g_off2r[MAXP + 1], g_cur2r[MAXP];
__device__ float g_dinv1[MAXN], g_dinv2f[MAXP], g_dinv2r[MAXP];
__device__ int2  g_e1[MAXE1];
__device__ int2  g_e2f[MAXE2];
__device__ int2  g_e2r[MAXE2];
__device__ int   g_aux[1024];
__device__ double g_stats[6 * 64];  // per norm: [0:32) sum, [32:64) sumsq

static inline int GRID(long long n, int b) { return (int)((n + b - 1) / b); }

// ---------------- degree count (int) ----------------
__global__ void k_cnt(const int* __restrict__ dst, int E, int* __restrict__ cnt) {
    int i = blockIdx.x * blockDim.x + threadIdx.x;
    if (i < E) atomicAdd(&cnt[dst[i]], 1);
}

__global__ void k_dinv(const int* __restrict__ cnt, float* __restrict__ dinv, int n) {
    int i = blockIdx.x * blockDim.x + threadIdx.x;
    if (i < n) dinv[i] = rsqrtf((float)cnt[i] + 1.0f);  // +1 self loop
}

// ---------------- exclusive-scan (3 phase, n <= 1024*1024) ----------------
__global__ void k_scan1(const int* __restrict__ cnt, int n, int* __restrict__ off,
                        int* __restrict__ aux) {
    __shared__ int sh[1024];
    int i = blockIdx.x * 1024 + threadIdx.x;
    int v = (i < n) ? cnt[i] : 0;
    sh[threadIdx.x] = v;
    __syncthreads();
    for (int o = 1; o < 1024; o <<= 1) {
        int t = (threadIdx.x >= o) ? sh[threadIdx.x - o] : 0;
        __syncthreads();
        sh[threadIdx.x] += t;
        __syncthreads();
    }
    if (i < n) off[i + 1] = sh[threadIdx.x];  // inclusive within block
    if (threadIdx.x == 1023) aux[blockIdx.x] = sh[1023];
}

__global__ void k_scan2(int* aux, int nb) {
    __shared__ int sh[1024];
    int v = (threadIdx.x < nb) ? aux[threadIdx.x] : 0;
    sh[threadIdx.x] = v;
    __syncthreads();
    for (int o = 1; o < 1024; o <<= 1) {
        int t = (threadIdx.x >= o) ? sh[threadIdx.x - o] : 0;
        __syncthreads();
        sh[threadIdx.x] += t;
        __syncthreads();
    }
    if (threadIdx.x < nb) aux[threadIdx.x] = sh[threadIdx.x] - v;  // exclusive
}

__global__ void k_scan3(int* __restrict__ off, const int* __restrict__ aux, int n) {
    int i = blockIdx.x * blockDim.x + threadIdx.x;
    if (i < n) off[i + 1] += aux[i >> 10];
}

// ---------------- CSR fill: pack (src, coef) as int2 ----------------
__global__ void k_fill(const int* __restrict__ src, const int* __restrict__ dst,
                       const float* __restrict__ dinv, const int* __restrict__ off,
                       int* __restrict__ cur, int2* __restrict__ edge, int E) {
    int e = blockIdx.x * blockDim.x + threadIdx.x;
    if (e >= E) return;
    int s = src[e], d = dst[e];
    int p = off[d] + atomicAdd(&cur[d], 1);
    int2 packed;
    packed.x = s;
    packed.y = __float_as_int(dinv[s] * dinv[d]);
    edge[p] = packed;
}

// ---------------- embedding gather ----------------
__global__ void k_embed(const int* __restrict__ ids, const float* __restrict__ emb,
                        float* __restrict__ out, int n) {
    int t = blockIdx.x * blockDim.x + threadIdx.x;
    if (t >= n * 8) return;
    int r = t >> 3, g = t & 7;
    float4 v = *(const float4*)(emb + (size_t)ids[r] * 32 + g * 4);
    *(float4*)(out + (size_t)r * 32 + g * 4) = v;
}

// ---------------- per-column sum & sumsq ----------------
__global__ void k_stats(const float* __restrict__ x, int n, int C, double* st) {
    int c = threadIdx.x;   // < C
    int ty = threadIdx.y;  // < 8
    double s = 0.0, s2 = 0.0;
    for (int r = blockIdx.x * blockDim.y + ty; r < n; r += gridDim.x * blockDim.y) {
        float v = x[(size_t)r * C + c];
        s += v;
        s2 += (double)v * (double)v;
    }
    __shared__ double sh[2][8][32];
    sh[0][ty][c] = s;
    sh[1][ty][c] = s2;
    __syncthreads();
    if (ty == 0) {
        for (int t = 1; t < 8; t++) { s += sh[0][t][c]; s2 += sh[1][t][c]; }
        atomicAdd(&st[c], s);
        atomicAdd(&st[32 + c], s2);
    }
}

// ---------------- h = normrelu(x) @ W (norm folded via per-col affine) ----
template <int CIN, int COUT, int NORM, int RELU>
__global__ void k_mm(const float* __restrict__ x, const float* __restrict__ W,
                     float* __restrict__ h, int n, const double* __restrict__ st,
                     const float* __restrict__ gw, const float* __restrict__ gb,
                     const float* __restrict__ ga) {
    __shared__ float Ws[CIN * COUT];
    __shared__ float S[32], T[32];
    for (int t = threadIdx.x; t < CIN * COUT; t += blockDim.x) Ws[t] = W[t];
    if (NORM && threadIdx.x < CIN) {
        int c = threadIdx.x;
        double av = (double)ga[c];
        double m = st[c] / n;
        double var = st[32 + c] / n - m * m * av * (2.0 - av);
        float s = gw[c] * rsqrtf((float)var + EPSV);
        S[c] = s;
        T[c] = gb[c] - (float)((double)s * av * m);
    }
    __syncthreads();
    int i = blockIdx.x * blockDim.x + threadIdx.x;
    if (i >= n) return;
    float acc[COUT];
#pragma unroll
    for (int j = 0; j < COUT; j++) acc[j] = 0.0f;
    const float* xr = x + (size_t)i * CIN;
#pragma unroll
    for (int k = 0; k < CIN; k++) {
        float xv = xr[k];
        if (NORM) xv = S[k] * xv + T[k];
        if (RELU) xv = fmaxf(xv, 0.0f);
#pragma unroll
        for (int j = 0; j < COUT; j++) acc[j] += xv * Ws[k * COUT + j];
    }
    float* hr = h + (size_t)i * COUT;
#pragma unroll
    for (int j = 0; j < COUT; j++) hr[j] = acc[j];
}

// ---------------- CSR gather: out[d] = dinv[d]^2 h[d] + b + sum coef*h[s] --
template <int C>
__global__ void k_gather(const int* __restrict__ off, const int2* __restrict__ edge,
                         const float* __restrict__ dinv, const float* __restrict__ h,
                         const float* __restrict__ bias, float* __restrict__ out, int n) {
    constexpr int G = C / 4;
    long long t = (long long)blockIdx.x * blockDim.x + threadIdx.x;
    int node = (int)(t / G);
    int g = (int)(t % G);
    if (node >= n) return;
    const float4* h4 = (const float4*)h;
    float dv = dinv[node];
    float c2 = dv * dv;
    float4 hv = h4[(size_t)node * G + g];
    float4 acc;
    acc.x = c2 * hv.x + bias[g * 4 + 0];
    acc.y = c2 * hv.y + bias[g * 4 + 1];
    acc.z = c2 * hv.z + bias[g * 4 + 2];
    acc.w = c2 * hv.w + bias[g * 4 + 3];
    int beg = off[node], end = off[node + 1];
    for (int j = beg; j < end; j++) {
        int2 ev = edge[j];
        float cf = __int_as_float(ev.y);
        float4 v = h4[(size_t)ev.x * G + g];
        acc.x += cf * v.x;
        acc.y += cf * v.y;
        acc.z += cf * v.z;
        acc.w += cf * v.w;
    }
    ((float4*)out)[(size_t)node * G + g] = acc;
}

// ---------------- pair: xp = norm(x[a])*norm(x[b]); ha=xp@W1; hb=xp@W2 -----
__global__ void k_pair_mm(const int* __restrict__ pos, const float* __restrict__ xn,
                          int nNode, const double* __restrict__ st,
                          const float* __restrict__ gw, const float* __restrict__ gb,
                          const float* __restrict__ ga, const float* __restrict__ W1,
                          const float* __restrict__ W2, float* __restrict__ ha,
                          float* __restrict__ hb, int P) {
    __shared__ float Ws1[24 * 24], Ws2[24 * 24], S[24], T[24];
    for (int t = threadIdx.x; t < 24 * 24; t += blockDim.x) {
        Ws1[t] = W1[t];
        Ws2[t] = W2[t];
    }
    if (threadIdx.x < 24) {
        int c = threadIdx.x;
        double av = (double)ga[c];
        double m = st[c] / nNode;
        double var = st[32 + c] / nNode - m * m * av * (2.0 - av);
        float s = gw[c] * rsqrtf((float)var + EPSV);
        S[c] = s;
        T[c] = gb[c] - (float)((double)s * av * m);
    }
    __syncthreads();
    int p = blockIdx.x * blockDim.x + threadIdx.x;
    if (p >= P) return;
    int ia = pos[2 * p], ib = pos[2 * p + 1];
    const float4* x4 = (const float4*)xn;
    float x[24];
#pragma unroll
    for (int q = 0; q < 6; q++) {
        float4 va = x4[(size_t)ia * 6 + q];
        float4 vb = x4[(size_t)ib * 6 + q];
        int c = q * 4;
        x[c + 0] = (S[c + 0] * va.x + T[c + 0]) * (S[c + 0] * vb.x + T[c + 0]);
        x[c + 1] = (S[c + 1] * va.y + T[c + 1]) * (S[c + 1] * vb.y + T[c + 1]);
        x[c + 2] = (S[c + 2] * va.z + T[c + 2]) * (S[c + 2] * vb.z + T[c + 2]);
        x[c + 3] = (S[c + 3] * va.w + T[c + 3]) * (S[c + 3] * vb.w + T[c + 3]);
    }
    float acc[24];
#pragma unroll
    for (int j = 0; j < 24; j++) acc[j] = 0.0f;
#pragma unroll
    for (int k = 0; k < 24; k++) {
        float xv = x[k];
#pragma unroll
        for (int j = 0; j < 24; j++) acc[j] += xv * Ws1[k * 24 + j];
    }
    float4* ha4 = (float4*)ha;
#pragma unroll
    for (int q = 0; q < 6; q++) {
        float4 r;
        r.x = acc[q * 4 + 0]; r.y = acc[q * 4 + 1]; r.z = acc[q * 4 + 2]; r.w = acc[q * 4 + 3];
        ha4[(size_t)p * 6 + q] = r;
    }
#pragma unroll
    for (int j = 0; j < 24; j++) acc[j] = 0.0f;
#pragma unroll
    for (int k = 0; k < 24; k++) {
        float xv = x[k];
#pragma unroll
        for (int j = 0; j < 24; j++) acc[j] += xv * Ws2[k * 24 + j];
    }
    float4* hb4 = (float4*)hb;
#pragma unroll
    for (int q = 0; q < 6; q++) {
        float4 r;
        r.x = acc[q * 4 + 0]; r.y = acc[q * 4 + 1]; r.z = acc[q * 4 + 2]; r.w = acc[q * 4 + 3];
        hb4[(size_t)p * 6 + q] = r;
    }
}

// ---------------- combine: relu(norm_A(A)) + relu(norm_B(B)) --------------
__global__ void k_combine(const float* __restrict__ A, const float* __restrict__ B, int n,
                          const double* __restrict__ stA, const double* __restrict__ stB,
                          const float* __restrict__ wA, const float* __restrict__ bA,
                          const float* __restrict__ aA, const float* __restrict__ wB,
                          const float* __restrict__ bB, const float* __restrict__ aB,
                          float* __restrict__ out) {
    long long i = (long long)blockIdx.x * blockDim.x + threadIdx.x;
    if (i >= (long long)n * 24) return;
    int c = (int)(i % 24);

    double avA = (double)aA[c];
    double mA = stA[c] / n;
    double vA = stA[32 + c] / n - mA * mA * avA * (2.0 - avA);
    float xa = wA[c] * (A[i] - (float)(avA * mA)) * rsqrtf((float)vA + EPSV) + bA[c];
    xa = fmaxf(xa, 0.0f);

    double avB = (double)aB[c];
    double mB = stB[c] / n;
    double vB = stB[32 + c] / n - mB * mB * avB * (2.0 - avB);
    float xb = wB[c] * (B[i] - (float)(avB * mB)) * rsqrtf((float)vB + EPSV) + bB[c];
    xb = fmaxf(xb, 0.0f);

    out[i] = xa + xb;
}

// ---------------- head ----------------
__global__ void k_final(const int* __restrict__ idx, const float* __restrict__ xs,
                        const float* __restrict__ pw, const float* __restrict__ pb,
                        float* __restrict__ out, int M) {
    long long t = (long long)blockIdx.x * blockDim.x + threadIdx.x;
    int m = (int)(t >> 5);
    int lane = (int)(t & 31);
    if (m >= M) return;
    int ia = idx[2 * m], ib = idx[2 * m + 1];
    float v = 0.0f;
    if (lane < 24) v = xs[(size_t)ia * 24 + lane] * xs[(size_t)ib * 24 + lane] * pw[lane];
#pragma unroll
    for (int o = 16; o > 0; o >>= 1) v += __shfl_down_sync(0xffffffffu, v, o);
    if (lane == 0) out[m] = v + pb[0];
}

// ---------------------------------------------------------------------------
extern "C" void kernel_launch(void* const* d_in, const int* in_sizes, int n_in,
                              void* d_out, int out_size) {
    const int* x_ids = (const int*)d_in[0];
    const int* edge1 = (const int*)d_in[1];
    const int* pos   = (const int*)d_in[2];
    const int* ei2   = (const int*)d_in[3];
    const int* idx   = (const int*)d_in[4];
    const float* emb = (const float*)d_in[5];
    const float *gn0w = (const float*)d_in[6], *gn0b = (const float*)d_in[7], *gn0a = (const float*)d_in[8];
    const float *c1w0 = (const float*)d_in[9], *c1b0 = (const float*)d_in[10];
    const float *gn1w0 = (const float*)d_in[11], *gn1b0 = (const float*)d_in[12], *gn1a0 = (const float*)d_in[13];
    const float *c1w1 = (const float*)d_in[14], *c1b1 = (const float*)d_in[15];
    const float *gn1w1 = (const float*)d_in[16], *gn1b1 = (const float*)d_in[17], *gn1a1 = (const float*)d_in[18];
    const float *c2w = (const float*)d_in[19], *c2b = (const float*)d_in[20];
    const float *gn2w = (const float*)d_in[21], *gn2b = (const float*)d_in[22], *gn2a = (const float*)d_in[23];
    const float *c2rw = (const float*)d_in[24], *c2rb = (const float*)d_in[25];
    const float *gn2rw = (const float*)d_in[26], *gn2rb = (const float*)d_in[27], *gn2ra = (const float*)d_in[28];
    const float *pw = (const float*)d_in[29], *pb = (const float*)d_in[30];

    const int N  = in_sizes[0];
    const int E1 = in_sizes[1] / 2;
    const int P  = in_sizes[2] / 2;
    const int E2 = in_sizes[3] / 2;
    const int M  = P / 2;

    float *node0, *node1, *node2, *pairHa, *pairHb, *pairA, *pairB;
    float *dinv1, *dinv2f, *dinv2r;
    int *cnt1, *off1, *cur1, *cnt2f, *off2f, *cur2f, *cnt2r, *off2r, *cur2r, *aux;
    int2 *e1, *e2f, *e2r;
    double* stats;
    cudaGetSymbolAddress((void**)&node0, g_node0);
    cudaGetSymbolAddress((void**)&node1, g_node1);
    cudaGetSymbolAddress((void**)&node2, g_node2);
    cudaGetSymbolAddress((void**)&pairHa, g_pairHa);
    cudaGetSymbolAddress((void**)&pairHb, g_pairHb);
    cudaGetSymbolAddress((void**)&pairA, g_pairA);
    cudaGetSymbolAddress((void**)&pairB, g_pairB);
    cudaGetSymbolAddress((void**)&dinv1, g_dinv1);
    cudaGetSymbolAddress((void**)&dinv2f, g_dinv2f);
    cudaGetSymbolAddress((void**)&dinv2r, g_dinv2r);
    cudaGetSymbolAddress((void**)&cnt1, g_cnt1);
    cudaGetSymbolAddress((void**)&off1, g_off1);
    cudaGetSymbolAddress((void**)&cur1, g_cur1);
    cudaGetSymbolAddress((void**)&cnt2f, g_cnt2f);
    cudaGetSymbolAddress((void**)&off2f, g_off2f);
    cudaGetSymbolAddress((void**)&cur2f, g_cur2f);
    cudaGetSymbolAddress((void**)&cnt2r, g_cnt2r);
    cudaGetSymbolAddress((void**)&off2r, g_off2r);
    cudaGetSymbolAddress((void**)&cur2r, g_cur2r);
    cudaGetSymbolAddress((void**)&aux, g_aux);
    cudaGetSymbolAddress((void**)&e1, g_e1);
    cudaGetSymbolAddress((void**)&e2f, g_e2f);
    cudaGetSymbolAddress((void**)&e2r, g_e2r);
    cudaGetSymbolAddress((void**)&stats, g_stats);

    const int B = 256;
    const int nb1 = (N + 1023) / 1024;
    const int nb2 = (P + 1023) / 1024;

    // zero counters / stats
    cudaMemsetAsync(cnt1, 0, (size_t)N * sizeof(int));
    cudaMemsetAsync(cnt2f, 0, (size_t)P * sizeof(int));
    cudaMemsetAsync(cnt2r, 0, (size_t)P * sizeof(int));
    cudaMemsetAsync(cur1, 0, (size_t)N * sizeof(int));
    cudaMemsetAsync(cur2f, 0, (size_t)P * sizeof(int));
    cudaMemsetAsync(cur2r, 0, (size_t)P * sizeof(int));
    cudaMemsetAsync(off1, 0, sizeof(int));
    cudaMemsetAsync(off2f, 0, sizeof(int));
    cudaMemsetAsync(off2r, 0, sizeof(int));
    cudaMemsetAsync(stats, 0, 6 * 64 * sizeof(double));

    // ---- degrees ----
    k_cnt<<<GRID(E1, B), B>>>(edge1 + E1, E1, cnt1);
    k_cnt<<<GRID(E2, B), B>>>(ei2 + E2, E2, cnt2f);  // fwd: dst = ei2[1]
    k_cnt<<<GRID(E2, B), B>>>(ei2, E2, cnt2r);       // rev: dst = ei2[0]
    k_dinv<<<GRID(N, B), B>>>(cnt1, dinv1, N);
    k_dinv<<<GRID(P, B), B>>>(cnt2f, dinv2f, P);
    k_dinv<<<GRID(P, B), B>>>(cnt2r, dinv2r, P);

    // ---- CSR offsets (scan) + fill ----
    k_scan1<<<nb1, 1024>>>(cnt1, N, off1, aux);
    k_scan2<<<1, 1024>>>(aux, nb1);
    k_scan3<<<GRID(N, B), B>>>(off1, aux, N);
    k_fill<<<GRID(E1, B), B>>>(edge1, edge1 + E1, dinv1, off1, cur1, e1, E1);

    k_scan1<<<nb2, 1024>>>(cnt2f, P, off2f, aux);
    k_scan2<<<1, 1024>>>(aux, nb2);
    k_scan3<<<GRID(P, B), B>>>(off2f, aux, P);
    k_fill<<<GRID(E2, B), B>>>(ei2, ei2 + E2, dinv2f, off2f, cur2f, e2f, E2);

    k_scan1<<<nb2, 1024>>>(cnt2r, P, off2r, aux);
    k_scan2<<<1, 1024>>>(aux, nb2);
    k_scan3<<<GRID(P, B), B>>>(off2r, aux, P);
    k_fill<<<GRID(E2, B), B>>>(ei2 + E2, ei2, dinv2r, off2r, cur2r, e2r, E2);

    // ---- embedding + GN0 stats ----
    k_embed<<<GRID((long long)N * 8, B), B>>>(x_ids, emb, node0, N);
    k_stats<<<256, dim3(32, 8)>>>(node0, N, 32, stats + 0);

    // ---- conv1 layer0: (GN0 folded) mm -> gather -> stats ----
    k_mm<32, 32, 1, 0><<<GRID(N, B), B>>>(node0, c1w0, node1, N, stats + 0, gn0w, gn0b, gn0a);
    k_gather<32><<<GRID((long long)N * 8, B), B>>>(off1, e1, dinv1, node1, c1b0, node2, N);
    k_stats<<<256, dim3(32, 8)>>>(node2, N, 32, stats + 64);

    // ---- conv1 layer1: (GN1_0+relu folded) mm -> gather -> stats ----
    k_mm<32, 24, 1, 1><<<GRID(N, B), B>>>(node2, c1w1, node0, N, stats + 64, gn1w0, gn1b0, gn1a0);
    k_gather<24><<<GRID((long long)N * 6, B), B>>>(off1, e1, dinv1, node0, c1b1, node1, N);
    k_stats<<<256, dim3(24, 8)>>>(node1, N, 24, stats + 128);

    // ---- pair features (+GN1_1 folded) + both 24x24 GEMMs ----
    k_pair_mm<<<GRID(P, 128), 128>>>(pos, node1, N, stats + 128, gn1w1, gn1b1, gn1a1,
                                     c2w, c2rw, pairHa, pairHb, P);

    // ---- conv2 fwd / rev gathers ----
    k_gather<24><<<GRID((long long)P * 6, B), B>>>(off2f, e2f, dinv2f, pairHa, c2b, pairA, P);
    k_stats<<<512, dim3(24, 8)>>>(pairA, P, 24, stats + 192);
    k_gather<24><<<GRID((long long)P * 6, B), B>>>(off2r, e2r, dinv2r, pairHb, c2rb, pairB, P);
    k_stats<<<512, dim3(24, 8)>>>(pairB, P, 24, stats + 256);

    // ---- combine (GN2 fwd/rev + relu + sum) -> reuse pairHa ----
    k_combine<<<GRID((long long)P * 24, B), B>>>(pairA, pairB, P, stats + 192, stats + 256,
                                                 gn2w, gn2b, gn2a, gn2rw, gn2rb, gn2ra, pairHa);

    // ---- head ----
    k_final<<<GRID((long long)M * 32, B), B>>>(idx, pairHa, pw, pb, (float*)d_out, M);
}

// round 3
// speedup vs baseline: 5.3205x; 4.2187x over previous
#include <cuda_runtime.h>
#include <cuda_fp16.h>

// ---------------------------------------------------------------------------
// LocalWLNet, CSR + fp16 messages + folded dinv + float stats:
//   zero -> [cnt/scan/fill x3] -> dinv -> embed -> stats
//   -> mm(GN0,32x32,*dinv) -> gather32 -> stats
//   -> mm(GN1a+relu,32x24,*dinv) -> gather24 -> stats
//   -> pair_mm(GN1b, dual 24x24, *dinv2f/*dinv2r, fp16 out)
//   -> gather_h24 fwd/rev (fp32 out) -> stats x2 -> affine -> fused head
// ---------------------------------------------------------------------------

#define MAXN   100000
#define MAXP   1000000
#define MAXE1  3200000
#define MAXE2  4000000
#define EPSV   1e-5f

__device__ float g_node0[MAXN * 32];
__device__ float g_node1[MAXN * 32];
__device__ float g_node2[MAXN * 32];
__device__ uint4 g_pairHa[MAXP * 3];   // fp16: 24 halfs = 3 x uint4 per row
__device__ uint4 g_pairHb[MAXP * 3];
__device__ float g_pairA[MAXP * 24];
__device__ float g_pairB[MAXP * 24];

__device__ int   g_cnt1[MAXN],  g_off1[MAXN + 1];
__device__ int   g_cnt2f[MAXP], g_off2f[MAXP + 1];
__device__ int   g_cnt2r[MAXP], g_off2r[MAXP + 1];
__device__ float g_dinv1[MAXN], g_dinv2f[MAXP], g_dinv2r[MAXP];
__device__ int   g_e1[MAXE1];
__device__ int   g_e2f[MAXE2];
__device__ int   g_e2r[MAXE2];
__device__ int   g_aux[1024];
__device__ float g_statsf[5 * 64];   // per slot: [0:32) sum, [32:64) sumsq
__device__ float g_aff[96];          // SA,TA,SB,TB x24 for fused head

static inline int GRID(long long n, int b) { return (int)((n + b - 1) / b); }

__device__ inline unsigned pack2(float a, float b) {
    __half2 h = __floats2half2_rn(a, b);
    return *reinterpret_cast<unsigned*>(&h);
}
__device__ inline float2 unpack2(unsigned u) {
    __half2 h = *reinterpret_cast<__half2*>(&u);
    return __half22float2(h);
}

// ---------------- zero all accumulators (one kernel, deterministic order) --
__global__ void k_zero(int* c1, int* c2f, int* c2r, float* st, int N, int P) {
    int i = blockIdx.x * blockDim.x + threadIdx.x;
    if (i < P) { c2f[i] = 0; c2r[i] = 0; }
    if (i < N) c1[i] = 0;
    if (i < 5 * 64) st[i] = 0.0f;
}

// ---------------- degree count ----------------
__global__ void k_cnt(const int* __restrict__ dst, int E, int* __restrict__ cnt) {
    int i = blockIdx.x * blockDim.x + threadIdx.x;
    if (i < E) atomicAdd(&cnt[dst[i]], 1);
}

__global__ void k_dinv(const int* __restrict__ cnt, float* __restrict__ dinv, int n) {
    int i = blockIdx.x * blockDim.x + threadIdx.x;
    if (i < n) dinv[i] = rsqrtf((float)cnt[i] + 1.0f);  // +1 self loop
}

// ---------------- exclusive scan (3 phase, n <= 1024*1024) ----------------
__global__ void k_scan1(const int* __restrict__ cnt, int n, int* __restrict__ off,
                        int* __restrict__ aux) {
    __shared__ int sh[1024];
    int i = blockIdx.x * 1024 + threadIdx.x;
    int v = (i < n) ? cnt[i] : 0;
    sh[threadIdx.x] = v;
    __syncthreads();
    for (int o = 1; o < 1024; o <<= 1) {
        int t = (threadIdx.x >= o) ? sh[threadIdx.x - o] : 0;
        __syncthreads();
        sh[threadIdx.x] += t;
        __syncthreads();
    }
    if (i < n) off[i] = sh[threadIdx.x] - v;  // exclusive within block
    if (threadIdx.x == 1023) aux[blockIdx.x] = sh[1023];
}

__global__ void k_scan2(int* aux, int nb) {
    __shared__ int sh[1024];
    int v = (threadIdx.x < nb) ? aux[threadIdx.x] : 0;
    sh[threadIdx.x] = v;
    __syncthreads();
    for (int o = 1; o < 1024; o <<= 1) {
        int t = (threadIdx.x >= o) ? sh[threadIdx.x - o] : 0;
        __syncthreads();
        sh[threadIdx.x] += t;
        __syncthreads();
    }
    if (threadIdx.x < nb) aux[threadIdx.x] = sh[threadIdx.x] - v;  // exclusive
}

__global__ void k_scan3(int* __restrict__ off, const int* __restrict__ aux, int n) {
    int i = blockIdx.x * blockDim.x + threadIdx.x;
    if (i < n) off[i] += aux[i >> 10];
}

// ---------------- CSR fill: off doubles as cursor; stores src only --------
__global__ void k_fill(const int* __restrict__ src, const int* __restrict__ dst,
                       int* __restrict__ off, int* __restrict__ edge, int E) {
    int e = blockIdx.x * blockDim.x + threadIdx.x;
    if (e >= E) return;
    int p = atomicAdd(&off[dst[e]], 1);
    edge[p] = src[e];
}

// ---------------- embedding gather ----------------
__global__ void k_embed(const int* __restrict__ ids, const float* __restrict__ emb,
                        float* __restrict__ out, int n) {
    int t = blockIdx.x * blockDim.x + threadIdx.x;
    if (t >= n * 8) return;
    int r = t >> 3, g = t & 7;
    float4 v = *(const float4*)(emb + (size_t)ids[r] * 32 + g * 4);
    *(float4*)(out + (size_t)r * 32 + g * 4) = v;
}

// ---------------- float stats: per-column sum & sumsq ----------------
template <int C>
__global__ void k_statsf(const float4* __restrict__ x4, int n, float* st) {
    constexpr int G = C / 4;
    int g = threadIdx.x;   // < G
    int ty = threadIdx.y;  // < 64
    float4 s = {0, 0, 0, 0}, q = {0, 0, 0, 0};
    for (int r = blockIdx.x * 64 + ty; r < n; r += gridDim.x * 64) {
        float4 v = x4[(size_t)r * G + g];
        s.x += v.x; s.y += v.y; s.z += v.z; s.w += v.w;
        q.x += v.x * v.x; q.y += v.y * v.y; q.z += v.z * v.z; q.w += v.w * v.w;
    }
    __shared__ float4 shS[64][8], shQ[64][8];
    shS[ty][g] = s;
    shQ[ty][g] = q;
    __syncthreads();
    if (ty == 0) {
        for (int t = 1; t < 64; t++) {
            float4 a = shS[t][g], b = shQ[t][g];
            s.x += a.x; s.y += a.y; s.z += a.z; s.w += a.w;
            q.x += b.x; q.y += b.y; q.z += b.z; q.w += b.w;
        }
        atomicAdd(&st[g * 4 + 0], s.x); atomicAdd(&st[g * 4 + 1], s.y);
        atomicAdd(&st[g * 4 + 2], s.z); atomicAdd(&st[g * 4 + 3], s.w);
        atomicAdd(&st[32 + g * 4 + 0], q.x); atomicAdd(&st[32 + g * 4 + 1], q.y);
        atomicAdd(&st[32 + g * 4 + 2], q.z); atomicAdd(&st[32 + g * 4 + 3], q.w);
    }
}

// ---------------- h' = dinv * (normrelu(x) @ W) ----------------
template <int CIN, int COUT, int RELU>
__global__ void k_mm(const float* __restrict__ x, const float* __restrict__ W,
                     const float* __restrict__ dinv, float* __restrict__ h, int n,
                     const float* __restrict__ st, const float* __restrict__ gw,
                     const float* __restrict__ gb, const float* __restrict__ ga) {
    __shared__ float Ws[CIN * COUT];
    __shared__ float S[CIN], T[CIN];
    for (int t = threadIdx.x; t < CIN * COUT; t += blockDim.x) Ws[t] = W[t];
    if (threadIdx.x < CIN) {
        int c = threadIdx.x;
        double av = (double)ga[c];
        double m = (double)st[c] / n;
        double var = (double)st[32 + c] / n - m * m * av * (2.0 - av);
        float s = gw[c] * rsqrtf((float)var + EPSV);
        S[c] = s;
        T[c] = gb[c] - (float)((double)s * av * m);
    }
    __syncthreads();
    int i = blockIdx.x * blockDim.x + threadIdx.x;
    if (i >= n) return;
    float acc[COUT];
#pragma unroll
    for (int j = 0; j < COUT; j++) acc[j] = 0.0f;
    const float* xr = x + (size_t)i * CIN;
#pragma unroll
    for (int k = 0; k < CIN; k++) {
        float xv = S[k] * xr[k] + T[k];
        if (RELU) xv = fmaxf(xv, 0.0f);
#pragma unroll
        for (int j = 0; j < COUT; j++) acc[j] += xv * Ws[k * COUT + j];
    }
    float dv = dinv[i];
    float* hr = h + (size_t)i * COUT;
#pragma unroll
    for (int j = 0; j < COUT; j++) hr[j] = dv * acc[j];
}

// ---------------- fp32 CSR gather: out[d] = dinv[d]*(h'[d]+sum h'[s]) + b --
template <int C>
__global__ void k_gather(const int* __restrict__ off, const int* __restrict__ edge,
                         const float* __restrict__ dinv, const float4* __restrict__ h4,
                         const float* __restrict__ bias, float4* __restrict__ out, int n) {
    constexpr int G = C / 4;
    long long t = (long long)blockIdx.x * blockDim.x + threadIdx.x;
    int node = (int)(t / G);
    int g = (int)(t % G);
    if (node >= n) return;
    float4 sum = h4[(size_t)node * G + g];
    int beg = node ? off[node - 1] : 0;  // off mutated by fill: off[d] = end[d]
    int end = off[node];
    for (int j = beg; j < end; j++) {
        int s = edge[j];
        float4 v = h4[(size_t)s * G + g];
        sum.x += v.x; sum.y += v.y; sum.z += v.z; sum.w += v.w;
    }
    float dv = dinv[node];
    float4 acc;
    acc.x = dv * sum.x + bias[g * 4 + 0];
    acc.y = dv * sum.y + bias[g * 4 + 1];
    acc.z = dv * sum.z + bias[g * 4 + 2];
    acc.w = dv * sum.w + bias[g * 4 + 3];
    out[(size_t)node * G + g] = acc;
}

// ---------------- pair: xp = norm(x[a])*norm(x[b]); dual GEMM; fp16 out ----
__global__ void k_pair_mm(const int* __restrict__ pos, const float* __restrict__ xn,
                          int nNode, const float* __restrict__ st,
                          const float* __restrict__ gw, const float* __restrict__ gb,
                          const float* __restrict__ ga, const float* __restrict__ W1,
                          const float* __restrict__ W2, const float* __restrict__ dvf,
                          const float* __restrict__ dvr, uint4* __restrict__ ha,
                          uint4* __restrict__ hb, int P) {
    __shared__ float Ws1[24 * 24], Ws2[24 * 24], S[24], T[24];
    for (int t = threadIdx.x; t < 24 * 24; t += blockDim.x) {
        Ws1[t] = W1[t];
        Ws2[t] = W2[t];
    }
    if (threadIdx.x < 24) {
        int c = threadIdx.x;
        double av = (double)ga[c];
        double m = (double)st[c] / nNode;
        double var = (double)st[32 + c] / nNode - m * m * av * (2.0 - av);
        float s = gw[c] * rsqrtf((float)var + EPSV);
        S[c] = s;
        T[c] = gb[c] - (float)((double)s * av * m);
    }
    __syncthreads();
    int p = blockIdx.x * blockDim.x + threadIdx.x;
    if (p >= P) return;
    int ia = pos[2 * p], ib = pos[2 * p + 1];
    const float4* x4 = (const float4*)xn;
    float x[24];
#pragma unroll
    for (int q = 0; q < 6; q++) {
        float4 va = x4[(size_t)ia * 6 + q];
        float4 vb = x4[(size_t)ib * 6 + q];
        int c = q * 4;
        x[c + 0] = (S[c + 0] * va.x + T[c + 0]) * (S[c + 0] * vb.x + T[c + 0]);
        x[c + 1] = (S[c + 1] * va.y + T[c + 1]) * (S[c + 1] * vb.y + T[c + 1]);
        x[c + 2] = (S[c + 2] * va.z + T[c + 2]) * (S[c + 2] * vb.z + T[c + 2]);
        x[c + 3] = (S[c + 3] * va.w + T[c + 3]) * (S[c + 3] * vb.w + T[c + 3]);
    }
    float a1[24], a2[24];
#pragma unroll
    for (int j = 0; j < 24; j++) { a1[j] = 0.0f; a2[j] = 0.0f; }
#pragma unroll
    for (int k = 0; k < 24; k++) {
        float xv = x[k];
#pragma unroll
        for (int j = 0; j < 24; j++) {
            a1[j] += xv * Ws1[k * 24 + j];
            a2[j] += xv * Ws2[k * 24 + j];
        }
    }
    float df = dvf[p], dr = dvr[p];
    uint4 u;
    u.x = pack2(df * a1[0], df * a1[1]);   u.y = pack2(df * a1[2], df * a1[3]);
    u.z = pack2(df * a1[4], df * a1[5]);   u.w = pack2(df * a1[6], df * a1[7]);
    ha[(size_t)p * 3 + 0] = u;
    u.x = pack2(df * a1[8], df * a1[9]);   u.y = pack2(df * a1[10], df * a1[11]);
    u.z = pack2(df * a1[12], df * a1[13]); u.w = pack2(df * a1[14], df * a1[15]);
    ha[(size_t)p * 3 + 1] = u;
    u.x = pack2(df * a1[16], df * a1[17]); u.y = pack2(df * a1[18], df * a1[19]);
    u.z = pack2(df * a1[20], df * a1[21]); u.w = pack2(df * a1[22], df * a1[23]);
    ha[(size_t)p * 3 + 2] = u;
    u.x = pack2(dr * a2[0], dr * a2[1]);   u.y = pack2(dr * a2[2], dr * a2[3]);
    u.z = pack2(dr * a2[4], dr * a2[5]);   u.w = pack2(dr * a2[6], dr * a2[7]);
    hb[(size_t)p * 3 + 0] = u;
    u.x = pack2(dr * a2[8], dr * a2[9]);   u.y = pack2(dr * a2[10], dr * a2[11]);
    u.z = pack2(dr * a2[12], dr * a2[13]); u.w = pack2(dr * a2[14], dr * a2[15]);
    hb[(size_t)p * 3 + 1] = u;
    u.x = pack2(dr * a2[16], dr * a2[17]); u.y = pack2(dr * a2[18], dr * a2[19]);
    u.z = pack2(dr * a2[20], dr * a2[21]); u.w = pack2(dr * a2[22], dr * a2[23]);
    hb[(size_t)p * 3 + 2] = u;
}

// ---------------- fp16 CSR gather (C=24): 3 groups x 8 halfs ----------------
__global__ void k_gather_h(const int* __restrict__ off, const int* __restrict__ edge,
                           const float* __restrict__ dinv, const uint4* __restrict__ h,
                           const float* __restrict__ bias, float4* __restrict__ out, int n) {
    long long t = (long long)blockIdx.x * blockDim.x + threadIdx.x;
    int node = (int)(t / 3);
    int g = (int)(t % 3);
    if (node >= n) return;
    float f[8];
    {
        uint4 u = h[(size_t)node * 3 + g];
        float2 a = unpack2(u.x), b = unpack2(u.y), c = unpack2(u.z), d = unpack2(u.w);
        f[0] = a.x; f[1] = a.y; f[2] = b.x; f[3] = b.y;
        f[4] = c.x; f[5] = c.y; f[6] = d.x; f[7] = d.y;
    }
    int beg = node ? off[node - 1] : 0;
    int end = off[node];
    for (int j = beg; j < end; j++) {
        int s = edge[j];
        uint4 u = h[(size_t)s * 3 + g];
        float2 a = unpack2(u.x), b = unpack2(u.y), c = unpack2(u.z), d = unpack2(u.w);
        f[0] += a.x; f[1] += a.y; f[2] += b.x; f[3] += b.y;
        f[4] += c.x; f[5] += c.y; f[6] += d.x; f[7] += d.y;
    }
    float dv = dinv[node];
    const float* bs = bias + g * 8;
    float4 o0, o1;
    o0.x = dv * f[0] + bs[0]; o0.y = dv * f[1] + bs[1];
    o0.z = dv * f[2] + bs[2]; o0.w = dv * f[3] + bs[3];
    o1.x = dv * f[4] + bs[4]; o1.y = dv * f[5] + bs[5];
    o1.z = dv * f[6] + bs[6]; o1.w = dv * f[7] + bs[7];
    out[(size_t)node * 6 + g * 2 + 0] = o0;
    out[(size_t)node * 6 + g * 2 + 1] = o1;
}

// ---------------- affine precompute for fused head ----------------
__global__ void k_affine(const float* __restrict__ stA, const float* __restrict__ stB, int n,
                         const float* __restrict__ wA, const float* __restrict__ bA,
                         const float* __restrict__ aA, const float* __restrict__ wB,
                         const float* __restrict__ bB, const float* __restrict__ aB,
                         float* __restrict__ aff) {
    int c = threadIdx.x;
    if (c >= 24) return;
    double avA = (double)aA[c];
    double mA = (double)stA[c] / n;
    double vA = (double)stA[32 + c] / n - mA * mA * avA * (2.0 - avA);
    float sA = wA[c] * rsqrtf((float)vA + EPSV);
    aff[c] = sA;
    aff[24 + c] = bA[c] - (float)((double)sA * avA * mA);
    double avB = (double)aB[c];
    double mB = (double)stB[c] / n;
    double vB = (double)stB[32 + c] / n - mB * mB * avB * (2.0 - avB);
    float sB = wB[c] * rsqrtf((float)vB + EPSV);
    aff[48 + c] = sB;
    aff[72 + c] = bB[c] - (float)((double)sB * avB * mB);
}

// ---------------- fused head: combine(GN2+relu+sum) + even*odd + dot -------
__global__ void k_final(const int* __restrict__ idx, const float* __restrict__ A,
                        const float* __restrict__ B, const float* __restrict__ aff,
                        const float* __restrict__ pw, const float* __restrict__ pb,
                        float* __restrict__ out, int M) {
    __shared__ float sAff[96], sPw[24];
    if (threadIdx.x < 96) sAff[threadIdx.x] = aff[threadIdx.x];
    if (threadIdx.x < 24) sPw[threadIdx.x] = pw[threadIdx.x];
    __syncthreads();
    long long t = (long long)blockIdx.x * blockDim.x + threadIdx.x;
    int m = (int)(t >> 5);
    int lane = (int)(t & 31);
    if (m >= M) return;
    int ia = idx[2 * m], ib = idx[2 * m + 1];
    float v = 0.0f;
    if (lane < 24) {
        int c = lane;
        float xa = fmaxf(sAff[c] * A[(size_t)ia * 24 + c] + sAff[24 + c], 0.0f) +
                   fmaxf(sAff[48 + c] * B[(size_t)ia * 24 + c] + sAff[72 + c], 0.0f);
        float xb = fmaxf(sAff[c] * A[(size_t)ib * 24 + c] + sAff[24 + c], 0.0f) +
                   fmaxf(sAff[48 + c] * B[(size_t)ib * 24 + c] + sAff[72 + c], 0.0f);
        v = xa * xb * sPw[c];
    }
#pragma unroll
    for (int o = 16; o > 0; o >>= 1) v += __shfl_down_sync(0xffffffffu, v, o);
    if (lane == 0) out[m] = v + pb[0];
}

// ---------------------------------------------------------------------------
extern "C" void kernel_launch(void* const* d_in, const int* in_sizes, int n_in,
                              void* d_out, int out_size) {
    const int* x_ids = (const int*)d_in[0];
    const int* edge1 = (const int*)d_in[1];
    const int* pos   = (const int*)d_in[2];
    const int* ei2   = (const int*)d_in[3];
    const int* idx   = (const int*)d_in[4];
    const float* emb = (const float*)d_in[5];
    const float *gn0w = (const float*)d_in[6], *gn0b = (const float*)d_in[7], *gn0a = (const float*)d_in[8];
    const float *c1w0 = (const float*)d_in[9], *c1b0 = (const float*)d_in[10];
    const float *gn1w0 = (const float*)d_in[11], *gn1b0 = (const float*)d_in[12], *gn1a0 = (const float*)d_in[13];
    const float *c1w1 = (const float*)d_in[14], *c1b1 = (const float*)d_in[15];
    const float *gn1w1 = (const float*)d_in[16], *gn1b1 = (const float*)d_in[17], *gn1a1 = (const float*)d_in[18];
    const float *c2w = (const float*)d_in[19], *c2b = (const float*)d_in[20];
    const float *gn2w = (const float*)d_in[21], *gn2b = (const float*)d_in[22], *gn2a = (const float*)d_in[23];
    const float *c2rw = (const float*)d_in[24], *c2rb = (const float*)d_in[25];
    const float *gn2rw = (const float*)d_in[26], *gn2rb = (const float*)d_in[27], *gn2ra = (const float*)d_in[28];
    const float *pw = (const float*)d_in[29], *pb = (const float*)d_in[30];

    const int N  = in_sizes[0];
    const int E1 = in_sizes[1] / 2;
    const int P  = in_sizes[2] / 2;
    const int E2 = in_sizes[3] / 2;
    const int M  = P / 2;

    float *node0, *node1, *node2, *pairA, *pairB;
    uint4 *pairHa, *pairHb;
    float *dinv1, *dinv2f, *dinv2r, *statsf, *aff;
    int *cnt1, *off1, *cnt2f, *off2f, *cnt2r, *off2r, *aux, *e1, *e2f, *e2r;
    cudaGetSymbolAddress((void**)&node0, g_node0);
    cudaGetSymbolAddress((void**)&node1, g_node1);
    cudaGetSymbolAddress((void**)&node2, g_node2);
    cudaGetSymbolAddress((void**)&pairHa, g_pairHa);
    cudaGetSymbolAddress((void**)&pairHb, g_pairHb);
    cudaGetSymbolAddress((void**)&pairA, g_pairA);
    cudaGetSymbolAddress((void**)&pairB, g_pairB);
    cudaGetSymbolAddress((void**)&dinv1, g_dinv1);
    cudaGetSymbolAddress((void**)&dinv2f, g_dinv2f);
    cudaGetSymbolAddress((void**)&dinv2r, g_dinv2r);
    cudaGetSymbolAddress((void**)&cnt1, g_cnt1);
    cudaGetSymbolAddress((void**)&off1, g_off1);
    cudaGetSymbolAddress((void**)&cnt2f, g_cnt2f);
    cudaGetSymbolAddress((void**)&off2f, g_off2f);
    cudaGetSymbolAddress((void**)&cnt2r, g_cnt2r);
    cudaGetSymbolAddress((void**)&off2r, g_off2r);
    cudaGetSymbolAddress((void**)&aux, g_aux);
    cudaGetSymbolAddress((void**)&e1, g_e1);
    cudaGetSymbolAddress((void**)&e2f, g_e2f);
    cudaGetSymbolAddress((void**)&e2r, g_e2r);
    cudaGetSymbolAddress((void**)&statsf, g_statsf);
    cudaGetSymbolAddress((void**)&aff, g_aff);

    const int B = 256;
    const int nb1 = (N + 1023) / 1024;
    const int nb2 = (P + 1023) / 1024;

    // 1: zero all accumulators
    k_zero<<<GRID(P, B), B>>>(cnt1, cnt2f, cnt2r, statsf, N, P);

    // 2-6: conv2 fwd CSR  (launch #6 = k_fill -> profiled by ncu -s 5 -c 1)
    k_cnt<<<GRID(E2, B), B>>>(ei2 + E2, E2, cnt2f);          // fwd dst = ei2[1]
    k_scan1<<<nb2, 1024>>>(cnt2f, P, off2f, aux);
    k_scan2<<<1, 1024>>>(aux, nb2);
    k_scan3<<<GRID(P, B), B>>>(off2f, aux, P);
    k_fill<<<GRID(E2, B), B>>>(ei2, ei2 + E2, off2f, e2f, E2);

    // conv2 rev CSR
    k_cnt<<<GRID(E2, B), B>>>(ei2, E2, cnt2r);               // rev dst = ei2[0]
    k_scan1<<<nb2, 1024>>>(cnt2r, P, off2r, aux);
    k_scan2<<<1, 1024>>>(aux, nb2);
    k_scan3<<<GRID(P, B), B>>>(off2r, aux, P);
    k_fill<<<GRID(E2, B), B>>>(ei2 + E2, ei2, off2r, e2r, E2);

    // conv1 CSR
    k_cnt<<<GRID(E1, B), B>>>(edge1 + E1, E1, cnt1);
    k_scan1<<<nb1, 1024>>>(cnt1, N, off1, aux);
    k_scan2<<<1, 1024>>>(aux, nb1);
    k_scan3<<<GRID(N, B), B>>>(off1, aux, N);
    k_fill<<<GRID(E1, B), B>>>(edge1, edge1 + E1, off1, e1, E1);

    // dinv
    k_dinv<<<GRID(N, B), B>>>(cnt1, dinv1, N);
    k_dinv<<<GRID(P, B), B>>>(cnt2f, dinv2f, P);
    k_dinv<<<GRID(P, B), B>>>(cnt2r, dinv2r, P);

    // embedding + GN0 stats
    k_embed<<<GRID((long long)N * 8, B), B>>>(x_ids, emb, node0, N);
    k_statsf<32><<<256, dim3(8, 64)>>>((const float4*)node0, N, statsf + 0);

    // conv1 layer0: (GN0) mm -> gather -> stats
    k_mm<32, 32, 0><<<GRID(N, B), B>>>(node0, c1w0, dinv1, node1, N, statsf + 0, gn0w, gn0b, gn0a);
    k_gather<32><<<GRID((long long)N * 8, B), B>>>(off1, e1, dinv1, (const float4*)node1, c1b0,
                                                   (float4*)node2, N);
    k_statsf<32><<<256, dim3(8, 64)>>>((const float4*)node2, N, statsf + 64);

    // conv1 layer1: (GN1_0 + relu) mm -> gather -> stats
    k_mm<32, 24, 1><<<GRID(N, B), B>>>(node2, c1w1, dinv1, node0, N, statsf + 64, gn1w0, gn1b0, gn1a0);
    k_gather<24><<<GRID((long long)N * 6, B), B>>>(off1, e1, dinv1, (const float4*)node0, c1b1,
                                                   (float4*)node1, N);
    k_statsf<24><<<256, dim3(6, 64)>>>((const float4*)node1, N, statsf + 128);

    // pair features (+GN1_1) + dual 24x24 GEMM, dinv-scaled fp16 out
    k_pair_mm<<<GRID(P, 128), 128>>>(pos, node1, N, statsf + 128, gn1w1, gn1b1, gn1a1,
                                     c2w, c2rw, dinv2f, dinv2r, pairHa, pairHb, P);

    // conv2 fwd / rev gathers + stats
    k_gather_h<<<GRID((long long)P * 3, B), B>>>(off2f, e2f, dinv2f, pairHa, c2b,
                                                 (float4*)pairA, P);
    k_statsf<24><<<512, dim3(6, 64)>>>((const float4*)pairA, P, statsf + 192);
    k_gather_h<<<GRID((long long)P * 3, B), B>>>(off2r, e2r, dinv2r, pairHb, c2rb,
                                                 (float4*)pairB, P);
    k_statsf<24><<<512, dim3(6, 64)>>>((const float4*)pairB, P, statsf + 256);

    // affine for fused head, then head
    k_affine<<<1, 32>>>(statsf + 192, statsf + 256, P, gn2w, gn2b, gn2a,
                        gn2rw, gn2rb, gn2ra, aff);
    k_final<<<GRID((long long)M * 32, B), B>>>(idx, pairA, pairB, aff, pw, pb, (float*)d_out, M);
}